// round 13
// baseline (speedup 1.0000x reference)
#include <cuda_runtime.h>

#define BB 32
#define SS 8192
#define DD 256
#define KSEL 1638          // max(1, int(8192*0.2))
#define NCHUNK 32
#define ROWS_PER_CHUNK 256 // SS / NCHUNK
#define ROWS_PER_WARP 32
#define ECHUNK 8           // kB blocks per batch
#define THI 1.99f          // guessed emphasis threshold (~80th pct of w)

// Scratch (no allocations allowed)
__device__ float g_w[BB * SS];                 // exp(tanh(x.W + b))
__device__ float g_Ppart[NCHUNK * BB * DD];    // per-chunk partial: sum x*w*m_hat
__device__ float g_Cpart[ECHUNK * BB * DD];    // per-chunk correction partials
__device__ float g_Psum[BB * DD];              // chunk-reduced P (kA tail)
__device__ float g_invZ[BB];
__device__ int   g_idx[BB * SS];               // correction row indices
__device__ float g_wc[BB * SS];                // signed correction weights (+-0.5*w)
__device__ int   g_cntE[BB];                   // correction count per batch
__device__ int   g_cnt1[BB];                   // arrival counters (self-resetting)
__device__ int   g_cnt2[BB];

// Branch-free w = exp(tanh(z)):  tanh(z) = 1 - 2/(e^{2z}+1)
__device__ __forceinline__ float exp_tanh(float z)
{
    const float ez = __expf(z + z);
    const float t  = 1.0f - __fdividef(2.0f, ez + 1.0f);
    return __expf(t);
}

// ---------------------------------------------------------------------------
// kA: streaming pass with guessed-emphasis accumulation.
// 8 warps/block, 32 rows/warp in groups of 4 rows with 8 lanes/row:
//   lane = rowlocal*8 + e; lane covers d = j*32 + e*4 (+0..3), j = 0..7.
// acc += x * w * (w>=THI ? 1.5 : 1).  W lives in smem (low reg pressure).
// Tail (last block per batch): Z, exact thr, out_a, Psum, signed correction
// list (rows between thr and THI).
// ---------------------------------------------------------------------------
__global__ __launch_bounds__(256, 2) void kA_kernel(const float* __restrict__ x,
                                                    const float* __restrict__ W,
                                                    const float* __restrict__ bias,
                                                    float* __restrict__ out_a)
{
    const int blk   = blockIdx.x;
    const int b     = blk / NCHUNK;
    const int chunk = blk % NCHUNK;
    const int warp  = threadIdx.x >> 5;
    const int lane  = threadIdx.x & 31;
    const int rowlocal = lane >> 3;   // 0..3
    const int e        = lane & 7;    // 0..7

    __shared__ float4 sW[64];
    if (threadIdx.x < 64) sW[threadIdx.x] = ((const float4*)W)[threadIdx.x];
    const float bv = bias[0];
    __syncthreads();

    float4 acc[8];
#pragma unroll
    for (int j = 0; j < 8; j++) acc[j] = make_float4(0.f, 0.f, 0.f, 0.f);

    const int s0 = chunk * ROWS_PER_CHUNK + warp * ROWS_PER_WARP;
    const float4* xb = (const float4*)(x + (size_t)b * SS * DD);

    for (int gi = 0; gi < 8; gi++) {
        const int srow = s0 + gi * 4 + rowlocal;
        const float4* xr = xb + (size_t)srow * (DD / 4);

        float4 v[8];
#pragma unroll
        for (int j = 0; j < 8; j++) v[j] = xr[j * 8 + e];   // d = j*32 + e*4

        float dp = 0.f;
#pragma unroll
        for (int j = 0; j < 8; j++) {
            const float4 wj = sW[j * 8 + e];
            dp += v[j].x * wj.x + v[j].y * wj.y + v[j].z * wj.z + v[j].w * wj.w;
        }

        dp += __shfl_xor_sync(0xffffffffu, dp, 1);
        dp += __shfl_xor_sync(0xffffffffu, dp, 2);
        dp += __shfl_xor_sync(0xffffffffu, dp, 4);

        const float wv = exp_tanh(dp + bv);
        if (e == 0) g_w[b * SS + srow] = wv;

        // guessed emphasis applied inline
        const float wm = (wv >= THI) ? (1.5f * wv) : wv;

#pragma unroll
        for (int j = 0; j < 8; j++) {
            acc[j].x += v[j].x * wm; acc[j].y += v[j].y * wm;
            acc[j].z += v[j].z * wm; acc[j].w += v[j].w * wm;
        }
    }

    // reduce acc across the 4 row-groups (lanes differing in bits 3,4)
#pragma unroll
    for (int j = 0; j < 8; j++) {
        acc[j].x += __shfl_xor_sync(0xffffffffu, acc[j].x, 8);
        acc[j].y += __shfl_xor_sync(0xffffffffu, acc[j].y, 8);
        acc[j].z += __shfl_xor_sync(0xffffffffu, acc[j].z, 8);
        acc[j].w += __shfl_xor_sync(0xffffffffu, acc[j].w, 8);
        acc[j].x += __shfl_xor_sync(0xffffffffu, acc[j].x, 16);
        acc[j].y += __shfl_xor_sync(0xffffffffu, acc[j].y, 16);
        acc[j].z += __shfl_xor_sync(0xffffffffu, acc[j].z, 16);
        acc[j].w += __shfl_xor_sync(0xffffffffu, acc[j].w, 16);
    }

    __shared__ float4 sacc[8][64];   // [warp][d/4]
    if (lane < 8) {
#pragma unroll
        for (int j = 0; j < 8; j++) sacc[warp][j * 8 + e] = acc[j];
    }
    __syncthreads();
    {
        float tot = 0.f;
        const float* sflat = (const float*)sacc;
#pragma unroll
        for (int wp = 0; wp < 8; wp++) tot += sflat[wp * DD + threadIdx.x];
        g_Ppart[((size_t)chunk * BB + b) * DD + threadIdx.x] = tot;
    }

    // ---- last-block-per-batch gate ----
    __threadfence();
    __shared__ int slast;
    if (threadIdx.x == 0) {
        const int old = atomicAdd(&g_cnt1[b], 1);
        slast = (old == NCHUNK - 1);
        if (slast) g_cnt1[b] = 0;           // reset for next graph replay
    }
    __syncthreads();
    if (!slast) return;

    // =================== tail for batch b ===================
    const int t = threadIdx.x;

    float wreg[32];
#pragma unroll
    for (int j = 0; j < 32; j++) wreg[j] = g_w[b * SS + j * 256 + t];

    __shared__ float sredf[8];
    __shared__ float sZ;
    __shared__ int   stot[32];
    if (t < 32) stot[t] = 0;

    // Z = sum(w)
    float z = 0.f;
#pragma unroll
    for (int j = 0; j < 32; j++) z += wreg[j];
#pragma unroll
    for (int off = 16; off; off >>= 1) z += __shfl_xor_sync(0xffffffffu, z, off);
    if (lane == 0) sredf[warp] = z;
    __syncthreads();
    if (t == 0) {
        float zz = 0.f;
        for (int i = 0; i < 8; i++) zz += sredf[i];
        sZ = zz;
    }

    // P chunk-reduction folded in (overlaps the barrier)
    {
        float p = 0.f;
#pragma unroll
        for (int c = 0; c < NCHUNK; c++)
            p += g_Ppart[((size_t)c * BB + b) * DD + t];
        g_Psum[b * DD + t] = p;
    }
    __syncthreads();
    const float invZ = 1.f / sZ;

    // exact KSEL-th largest via binary search on float bit patterns
    unsigned lo = 0x3E800000u;  // 0.25f
    unsigned hi = 0x40800000u;  // 4.0f
    int it = 0;
    while (hi - lo > 1u) {
        const unsigned mid = lo + ((hi - lo) >> 1);
        const float fm = __uint_as_float(mid);
        int c = 0;
#pragma unroll
        for (int j = 0; j < 32; j++) c += (wreg[j] >= fm);
        c = __reduce_add_sync(0xffffffffu, c);
        if (lane == 0) atomicAdd(&stot[it], c);
        __syncthreads();
        if (stot[it] >= KSEL) lo = mid; else hi = mid;
        it++;
    }
    const float thr = __uint_as_float(lo);
    if (t == 0) g_invZ[b] = invZ;

    // out_a + correction band membership.
    // thr < THI : rows w in [thr, THI)  were under-emphasized -> +0.5*w
    // thr > THI : rows w in [THI, thr)  were over-emphasized  -> -0.5*w
    const float tlo  = fminf(thr, THI);
    const float thi2 = fmaxf(thr, THI);
    const float sgn  = (thr < THI) ? 0.5f : -0.5f;

    unsigned bandmask = 0u;
    int cnt = 0;
#pragma unroll
    for (int j = 0; j < 32; j++) {
        const float wv = wreg[j];
        const bool topk = (wv >= thr);
        out_a[b * SS + j * 256 + t] = wv * invZ * (topk ? 1.5f : 1.0f);
        const bool inband = (wv >= tlo) && (wv < thi2);
        bandmask |= (inband ? 1u : 0u) << j;
        cnt += inband ? 1 : 0;
    }

    // deterministic ordered compaction of correction rows
    int v2 = cnt;
#pragma unroll
    for (int off = 1; off < 32; off <<= 1) {
        const int n = __shfl_up_sync(0xffffffffu, v2, off);
        if (lane >= off) v2 += n;
    }
    __shared__ int swsum[8];
    __shared__ int swbase[8];
    if (lane == 31) swsum[warp] = v2;
    __syncthreads();
    if (t == 0) {
        int s = 0;
        for (int i = 0; i < 8; i++) { swbase[i] = s; s += swsum[i]; }
        g_cntE[b] = s;
    }
    __syncthreads();
    int base = swbase[warp] + v2 - cnt;
    int*   dsti = g_idx + b * SS;
    float* dstw = g_wc  + b * SS;
#pragma unroll
    for (int j = 0; j < 32; j++) {
        if ((bandmask >> j) & 1u) {
            dsti[base] = j * 256 + t;
            dstw[base] = sgn * wreg[j];
            base++;
        }
    }
}

// ---------------------------------------------------------------------------
// kB: signed correction gather (tiny list, ~100-300 rows/batch typical).
// Branchless 4-slot preload (clamped) so the row LDGs batch.
// Per-batch last-block tail writes the final out_sum.
// ---------------------------------------------------------------------------
__global__ __launch_bounds__(256) void kB_kernel(const float* __restrict__ x,
                                                 float* __restrict__ out_sum)
{
    const int b     = blockIdx.x / ECHUNK;
    const int chunk = blockIdx.x % ECHUNK;
    const int warp  = threadIdx.x >> 5;
    const int lane  = threadIdx.x & 31;
    const int g     = chunk * 8 + warp;   // 0..63

    const int cnt = g_cntE[b];
    const int*   idx = g_idx + b * SS;
    const float* wc  = g_wc  + b * SS;
    const float4* xb = (const float4*)(x + (size_t)b * SS * DD);

    float acc[8];
#pragma unroll
    for (int j = 0; j < 8; j++) acc[j] = 0.f;

    for (int sbase = g; sbase < cnt; sbase += 4 * 64) {
        int   rr[4];
        float ww[4];
#pragma unroll
        for (int k = 0; k < 4; k++) {
            const int s = sbase + k * 64;
            const bool vld = (s < cnt);
            rr[k] = vld ? idx[s] : 0;
            ww[k] = vld ? wc[s]  : 0.f;
        }
#pragma unroll
        for (int k = 0; k < 4; k++) {    // branchless: LDGs batch
            const float4* x0 = xb + (size_t)rr[k] * (DD / 4);
            const float4 a0 = x0[lane];
            const float4 a1 = x0[32 + lane];
            const float w0 = ww[k];
            acc[0] += a0.x * w0; acc[1] += a0.y * w0;
            acc[2] += a0.z * w0; acc[3] += a0.w * w0;
            acc[4] += a1.x * w0; acc[5] += a1.y * w0;
            acc[6] += a1.z * w0; acc[7] += a1.w * w0;
        }
    }

    __shared__ float sacc[8][DD];
#pragma unroll
    for (int j = 0; j < 4; j++) {
        sacc[warp][lane * 4 + j]       = acc[j];
        sacc[warp][128 + lane * 4 + j] = acc[4 + j];
    }
    __syncthreads();
    {
        float tot = 0.f;
#pragma unroll
        for (int wp = 0; wp < 8; wp++) tot += sacc[wp][threadIdx.x];
        g_Cpart[((size_t)chunk * BB + b) * DD + threadIdx.x] = tot;
    }

    // ---- last-block-per-batch gate ----
    __threadfence();
    __shared__ int slast;
    if (threadIdx.x == 0) {
        const int old = atomicAdd(&g_cnt2[b], 1);
        slast = (old == ECHUNK - 1);
        if (slast) g_cnt2[b] = 0;
    }
    __syncthreads();
    if (!slast) return;

    // =================== final combine for batch b ===================
    const int t = threadIdx.x;
    float csum = 0.f;
#pragma unroll
    for (int c = 0; c < ECHUNK; c++)
        csum += g_Cpart[((size_t)c * BB + b) * DD + t];
    out_sum[b * DD + t] = g_invZ[b] * (g_Psum[b * DD + t] + csum);
}

// ---------------------------------------------------------------------------
extern "C" void kernel_launch(void* const* d_in, const int* in_sizes, int n_in,
                              void* d_out, int out_size)
{
    const float* x    = (const float*)d_in[0];
    const float* W    = (const float*)d_in[1];
    const float* bias = (const float*)d_in[2];

    float* out      = (float*)d_out;
    float* out_sum  = out;              // [BB, DD]
    float* out_a    = out + BB * DD;    // [BB, SS]

    kA_kernel<<<BB * NCHUNK, 256>>>(x, W, bias, out_a);
    kB_kernel<<<BB * ECHUNK, 256>>>(x, out_sum);
}

// round 15
// speedup vs baseline: 1.2507x; 1.2507x over previous
#include <cuda_runtime.h>

#define BB 32
#define SS 8192
#define DD 256
#define KSEL 1638          // max(1, int(8192*0.2))
#define NCHUNK 32
#define ROWS_PER_CHUNK 256 // SS / NCHUNK
#define ROWS_PER_WARP 32
#define ECHUNK 8           // kB blocks per batch
#define THI 1.99f          // guessed emphasis threshold (~80th pct of w)

// Scratch (no allocations allowed)
__device__ float g_w[BB * SS];                 // exp(tanh(x.W + b))
__device__ float g_Ppart[NCHUNK * BB * DD];    // per-chunk partial: sum x*w*m_hat
__device__ float g_Cpart[ECHUNK * BB * DD];    // per-chunk correction partials
__device__ float g_Psum[BB * DD];              // chunk-reduced P (k2)
__device__ float g_invZ[BB];
__device__ int   g_idx[BB * SS];               // correction row indices
__device__ float g_wc[BB * SS];                // signed correction weights (+-0.5*w)
__device__ int   g_cntE[BB];                   // correction count per batch
__device__ int   g_cnt2[BB];                   // kB arrival counter (self-resetting)

// Branch-free w = exp(tanh(z)):  tanh(z) = 1 - 2/(e^{2z}+1)
__device__ __forceinline__ float exp_tanh(float z)
{
    const float ez = __expf(z + z);
    const float t  = 1.0f - __fdividef(2.0f, ez + 1.0f);
    return __expf(t);
}

// ---------------------------------------------------------------------------
// k1: streaming pass (R3 structure — best measured). 8 warps/block,
// 32 rows/warp in groups of 4 rows with 8 lanes/row:
//   lane = rowlocal*8 + e; lane covers d = j*32 + e*4 (+0..3), j = 0..7.
// acc += x * w * (w>=THI ? 1.5 : 1)   (guessed emphasis, fixed in kB).
// ---------------------------------------------------------------------------
__global__ __launch_bounds__(256, 2) void k1_kernel(const float* __restrict__ x,
                                                    const float* __restrict__ W,
                                                    const float* __restrict__ bias)
{
    const int blk   = blockIdx.x;
    const int b     = blk / NCHUNK;
    const int chunk = blk % NCHUNK;
    const int warp  = threadIdx.x >> 5;
    const int lane  = threadIdx.x & 31;
    const int rowlocal = lane >> 3;   // 0..3
    const int e        = lane & 7;    // 0..7

    const float4* Wf4 = (const float4*)W;
    float4 wreg4[8];
#pragma unroll
    for (int j = 0; j < 8; j++) wreg4[j] = Wf4[j * 8 + e];
    const float bv = bias[0];

    float4 acc[8];
#pragma unroll
    for (int j = 0; j < 8; j++) acc[j] = make_float4(0.f, 0.f, 0.f, 0.f);

    const int s0 = chunk * ROWS_PER_CHUNK + warp * ROWS_PER_WARP;
    const float4* xb = (const float4*)(x + (size_t)b * SS * DD);

    for (int gi = 0; gi < 8; gi++) {
        const int srow = s0 + gi * 4 + rowlocal;
        const float4* xr = xb + (size_t)srow * (DD / 4);

        float4 v[8];
#pragma unroll
        for (int j = 0; j < 8; j++) v[j] = xr[j * 8 + e];   // d = j*32 + e*4

        float dp = 0.f;
#pragma unroll
        for (int j = 0; j < 8; j++)
            dp += v[j].x * wreg4[j].x + v[j].y * wreg4[j].y
                + v[j].z * wreg4[j].z + v[j].w * wreg4[j].w;

        dp += __shfl_xor_sync(0xffffffffu, dp, 1);
        dp += __shfl_xor_sync(0xffffffffu, dp, 2);
        dp += __shfl_xor_sync(0xffffffffu, dp, 4);

        const float wv = exp_tanh(dp + bv);
        if (e == 0) g_w[b * SS + srow] = wv;

        const float wm = (wv >= THI) ? (1.5f * wv) : wv;   // guessed emphasis

#pragma unroll
        for (int j = 0; j < 8; j++) {
            acc[j].x += v[j].x * wm; acc[j].y += v[j].y * wm;
            acc[j].z += v[j].z * wm; acc[j].w += v[j].w * wm;
        }
    }

    // reduce acc across the 4 row-groups (lanes differing in bits 3,4)
#pragma unroll
    for (int j = 0; j < 8; j++) {
        acc[j].x += __shfl_xor_sync(0xffffffffu, acc[j].x, 8);
        acc[j].y += __shfl_xor_sync(0xffffffffu, acc[j].y, 8);
        acc[j].z += __shfl_xor_sync(0xffffffffu, acc[j].z, 8);
        acc[j].w += __shfl_xor_sync(0xffffffffu, acc[j].w, 8);
        acc[j].x += __shfl_xor_sync(0xffffffffu, acc[j].x, 16);
        acc[j].y += __shfl_xor_sync(0xffffffffu, acc[j].y, 16);
        acc[j].z += __shfl_xor_sync(0xffffffffu, acc[j].z, 16);
        acc[j].w += __shfl_xor_sync(0xffffffffu, acc[j].w, 16);
    }

    __shared__ float4 sacc[8][64];   // [warp][d/4]
    if (lane < 8) {
#pragma unroll
        for (int j = 0; j < 8; j++) sacc[warp][j * 8 + e] = acc[j];
    }
    __syncthreads();

    float tot = 0.f;
    const float* sflat = (const float*)sacc;
#pragma unroll
    for (int wp = 0; wp < 8; wp++) tot += sflat[wp * DD + threadIdx.x];
    g_Ppart[((size_t)chunk * BB + b) * DD + threadIdx.x] = tot;
}

// ---------------------------------------------------------------------------
// k2: per batch (32 blocks x 256 threads): Z, Psum reduce, exact KSEL-th
// largest via bitwise binary search, emphasized_a, signed correction-band
// compaction into g_idx/g_wc.
// ---------------------------------------------------------------------------
__global__ __launch_bounds__(256) void k2_kernel(float* __restrict__ out_a)
{
    const int b    = blockIdx.x;
    const int t    = threadIdx.x;
    const int warp = t >> 5;
    const int lane = t & 31;

    float wreg[32];
#pragma unroll
    for (int j = 0; j < 32; j++) wreg[j] = g_w[b * SS + j * 256 + t];

    __shared__ float sredf[8];
    __shared__ float sZ;
    __shared__ int   stot[32];
    if (t < 32) stot[t] = 0;

    // Z = sum(w)
    float z = 0.f;
#pragma unroll
    for (int j = 0; j < 32; j++) z += wreg[j];
#pragma unroll
    for (int off = 16; off; off >>= 1) z += __shfl_xor_sync(0xffffffffu, z, off);
    if (lane == 0) sredf[warp] = z;
    __syncthreads();
    if (t == 0) {
        float zz = 0.f;
        for (int i = 0; i < 8; i++) zz += sredf[i];
        sZ = zz;
    }

    // P chunk-reduction folded in (overlaps the barrier)
    {
        float p = 0.f;
#pragma unroll
        for (int c = 0; c < NCHUNK; c++)
            p += g_Ppart[((size_t)c * BB + b) * DD + t];
        g_Psum[b * DD + t] = p;
    }
    __syncthreads();
    const float invZ = 1.f / sZ;

    // exact KSEL-th largest via binary search on float bit patterns
    unsigned lo = 0x3E800000u;  // 0.25f
    unsigned hi = 0x40800000u;  // 4.0f
    int it = 0;
    while (hi - lo > 1u) {
        const unsigned mid = lo + ((hi - lo) >> 1);
        const float fm = __uint_as_float(mid);
        int c = 0;
#pragma unroll
        for (int j = 0; j < 32; j++) c += (wreg[j] >= fm);
        c = __reduce_add_sync(0xffffffffu, c);
        if (lane == 0) atomicAdd(&stot[it], c);
        __syncthreads();
        if (stot[it] >= KSEL) lo = mid; else hi = mid;
        it++;
    }
    const float thr = __uint_as_float(lo);
    if (t == 0) g_invZ[b] = invZ;

    // out_a + correction band membership.
    // thr < THI : rows w in [thr, THI)  under-emphasized -> +0.5*w
    // thr > THI : rows w in [THI, thr)  over-emphasized  -> -0.5*w
    const float tlo  = fminf(thr, THI);
    const float thi2 = fmaxf(thr, THI);
    const float sgn  = (thr < THI) ? 0.5f : -0.5f;

    unsigned bandmask = 0u;
    int cnt = 0;
#pragma unroll
    for (int j = 0; j < 32; j++) {
        const float wv = wreg[j];
        out_a[b * SS + j * 256 + t] = wv * invZ * ((wv >= thr) ? 1.5f : 1.0f);
        const bool inband = (wv >= tlo) && (wv < thi2);
        bandmask |= (inband ? 1u : 0u) << j;
        cnt += inband ? 1 : 0;
    }

    // deterministic ordered compaction of correction rows
    int v2 = cnt;
#pragma unroll
    for (int off = 1; off < 32; off <<= 1) {
        const int n = __shfl_up_sync(0xffffffffu, v2, off);
        if (lane >= off) v2 += n;
    }
    __shared__ int swsum[8];
    __shared__ int swbase[8];
    if (lane == 31) swsum[warp] = v2;
    __syncthreads();
    if (t == 0) {
        int s = 0;
        for (int i = 0; i < 8; i++) { swbase[i] = s; s += swsum[i]; }
        g_cntE[b] = s;
    }
    __syncthreads();
    int base = swbase[warp] + v2 - cnt;
    int*   dsti = g_idx + b * SS;
    float* dstw = g_wc  + b * SS;
#pragma unroll
    for (int j = 0; j < 32; j++) {
        if ((bandmask >> j) & 1u) {
            dsti[base] = j * 256 + t;
            dstw[base] = sgn * wreg[j];
            base++;
        }
    }
}

// ---------------------------------------------------------------------------
// kB: signed correction gather (tiny list) + per-batch last-block final
// combine. Branchless 4-slot preload so the row LDGs batch.
// ---------------------------------------------------------------------------
__global__ __launch_bounds__(256) void kB_kernel(const float* __restrict__ x,
                                                 float* __restrict__ out_sum)
{
    const int b     = blockIdx.x / ECHUNK;
    const int chunk = blockIdx.x % ECHUNK;
    const int warp  = threadIdx.x >> 5;
    const int lane  = threadIdx.x & 31;
    const int g     = chunk * 8 + warp;   // 0..63

    const int cnt = g_cntE[b];
    const int*   idx = g_idx + b * SS;
    const float* wc  = g_wc  + b * SS;
    const float4* xb = (const float4*)(x + (size_t)b * SS * DD);

    float acc[8];
#pragma unroll
    for (int j = 0; j < 8; j++) acc[j] = 0.f;

    for (int sbase = g; sbase < cnt; sbase += 4 * 64) {
        int   rr[4];
        float ww[4];
#pragma unroll
        for (int k = 0; k < 4; k++) {
            const int s = sbase + k * 64;
            const bool vld = (s < cnt);
            rr[k] = vld ? idx[s] : 0;
            ww[k] = vld ? wc[s]  : 0.f;
        }
#pragma unroll
        for (int k = 0; k < 4; k++) {    // branchless: LDGs batch
            const float4* x0 = xb + (size_t)rr[k] * (DD / 4);
            const float4 a0 = x0[lane];
            const float4 a1 = x0[32 + lane];
            const float w0 = ww[k];
            acc[0] += a0.x * w0; acc[1] += a0.y * w0;
            acc[2] += a0.z * w0; acc[3] += a0.w * w0;
            acc[4] += a1.x * w0; acc[5] += a1.y * w0;
            acc[6] += a1.z * w0; acc[7] += a1.w * w0;
        }
    }

    __shared__ float sacc[8][DD];
#pragma unroll
    for (int j = 0; j < 4; j++) {
        sacc[warp][lane * 4 + j]       = acc[j];
        sacc[warp][128 + lane * 4 + j] = acc[4 + j];
    }
    __syncthreads();
    {
        float tot = 0.f;
#pragma unroll
        for (int wp = 0; wp < 8; wp++) tot += sacc[wp][threadIdx.x];
        g_Cpart[((size_t)chunk * BB + b) * DD + threadIdx.x] = tot;
    }

    // ---- last-block-per-batch gate ----
    __threadfence();
    __shared__ int slast;
    if (threadIdx.x == 0) {
        const int old = atomicAdd(&g_cnt2[b], 1);
        slast = (old == ECHUNK - 1);
        if (slast) g_cnt2[b] = 0;
    }
    __syncthreads();
    if (!slast) return;

    // =================== final combine for batch b ===================
    const int t = threadIdx.x;
    float csum = 0.f;
#pragma unroll
    for (int c = 0; c < ECHUNK; c++)
        csum += g_Cpart[((size_t)c * BB + b) * DD + t];
    out_sum[b * DD + t] = g_invZ[b] * (g_Psum[b * DD + t] + csum);
}

// ---------------------------------------------------------------------------
extern "C" void kernel_launch(void* const* d_in, const int* in_sizes, int n_in,
                              void* d_out, int out_size)
{
    const float* x    = (const float*)d_in[0];
    const float* W    = (const float*)d_in[1];
    const float* bias = (const float*)d_in[2];

    float* out      = (float*)d_out;
    float* out_sum  = out;              // [BB, DD]
    float* out_a    = out + BB * DD;    // [BB, SS]

    k1_kernel<<<BB * NCHUNK, 256>>>(x, W, bias);
    k2_kernel<<<BB, 256>>>(out_a);
    kB_kernel<<<BB * ECHUNK, 256>>>(x, out_sum);
}

// round 17
// speedup vs baseline: 1.2609x; 1.0081x over previous
#include <cuda_runtime.h>

#define BB 32
#define SS 8192
#define DD 256
#define KSEL 1638          // max(1, int(8192*0.2))
#define NCHUNK 32
#define ROWS_PER_CHUNK 256 // SS / NCHUNK
#define ROWS_PER_WARP 32
#define THI 1.99f          // guessed emphasis threshold (~80th pct of w)

// Scratch (no allocations allowed)
__device__ float g_w[BB * SS];                 // exp(tanh(x.W + b))
__device__ float g_Ppart[NCHUNK * BB * DD];    // per-chunk partial: sum x*w*m_hat
__device__ int   g_idx[BB * SS];               // correction row indices
__device__ float g_wc[BB * SS];                // signed correction weights (+-0.5*w)

// Branch-free w = exp(tanh(z)):  tanh(z) = 1 - 2/(e^{2z}+1)
__device__ __forceinline__ float exp_tanh(float z)
{
    const float ez = __expf(z + z);
    const float t  = 1.0f - __fdividef(2.0f, ez + 1.0f);
    return __expf(t);
}

// ---------------------------------------------------------------------------
// k1: streaming pass, 16 lanes/row (2 rows per warp-iteration) for low
// register pressure -> 3 blocks/SM.  lane = r*16 + e; lane covers
// d = j*64 + e*4 (+0..3), j = 0..3.  Row reduce = 4 shfl_xor (1,2,4,8).
// acc += x * w * (w>=THI ? 1.5 : 1)  (guessed emphasis, corrected in k23).
// ---------------------------------------------------------------------------
__global__ __launch_bounds__(256) void k1_kernel(const float* __restrict__ x,
                                                 const float* __restrict__ W,
                                                 const float* __restrict__ bias)
{
    const int blk   = blockIdx.x;
    const int b     = blk / NCHUNK;
    const int chunk = blk % NCHUNK;
    const int warp  = threadIdx.x >> 5;
    const int lane  = threadIdx.x & 31;
    const int r     = lane >> 4;      // 0..1
    const int e     = lane & 15;      // 0..15

    const float4* Wf4 = (const float4*)W;
    float4 wv4[4];
#pragma unroll
    for (int j = 0; j < 4; j++) wv4[j] = Wf4[j * 16 + e];
    const float bv = bias[0];

    float4 acc[4];
#pragma unroll
    for (int j = 0; j < 4; j++) acc[j] = make_float4(0.f, 0.f, 0.f, 0.f);

    const int s0 = chunk * ROWS_PER_CHUNK + warp * ROWS_PER_WARP;
    const float4* xb = (const float4*)(x + (size_t)b * SS * DD);

#pragma unroll 2
    for (int gi = 0; gi < 16; gi++) {          // 2 rows per iteration
        const int srow = s0 + gi * 2 + r;
        const float4* xr = xb + (size_t)srow * (DD / 4);

        float4 v[4];
#pragma unroll
        for (int j = 0; j < 4; j++) v[j] = xr[j * 16 + e];   // d = j*64 + e*4

        float dp = 0.f;
#pragma unroll
        for (int j = 0; j < 4; j++)
            dp += v[j].x * wv4[j].x + v[j].y * wv4[j].y
                + v[j].z * wv4[j].z + v[j].w * wv4[j].w;

        // reduce across the 16 lanes of this row
        dp += __shfl_xor_sync(0xffffffffu, dp, 1);
        dp += __shfl_xor_sync(0xffffffffu, dp, 2);
        dp += __shfl_xor_sync(0xffffffffu, dp, 4);
        dp += __shfl_xor_sync(0xffffffffu, dp, 8);

        const float wv = exp_tanh(dp + bv);
        if (e == 0) g_w[b * SS + srow] = wv;

        const float wm = (wv >= THI) ? (1.5f * wv) : wv;   // guessed emphasis

#pragma unroll
        for (int j = 0; j < 4; j++) {
            acc[j].x += v[j].x * wm; acc[j].y += v[j].y * wm;
            acc[j].z += v[j].z * wm; acc[j].w += v[j].w * wm;
        }
    }

    // combine the two row-groups (lanes differing in bit 4)
#pragma unroll
    for (int j = 0; j < 4; j++) {
        acc[j].x += __shfl_xor_sync(0xffffffffu, acc[j].x, 16);
        acc[j].y += __shfl_xor_sync(0xffffffffu, acc[j].y, 16);
        acc[j].z += __shfl_xor_sync(0xffffffffu, acc[j].z, 16);
        acc[j].w += __shfl_xor_sync(0xffffffffu, acc[j].w, 16);
    }

    __shared__ float4 sacc[8][64];   // [warp][d/4]
    if (r == 0) {
#pragma unroll
        for (int j = 0; j < 4; j++) sacc[warp][j * 16 + e] = acc[j];
    }
    __syncthreads();

    float tot = 0.f;
    const float* sflat = (const float*)sacc;
#pragma unroll
    for (int wp = 0; wp < 8; wp++) tot += sflat[wp * DD + threadIdx.x];
    g_Ppart[((size_t)chunk * BB + b) * DD + threadIdx.x] = tot;
}

// ---------------------------------------------------------------------------
// k23: one block per batch. Z, Psum reduce, exact KSEL-th largest threshold,
// emphasized_a, correction-band compaction (global, block-local), then the
// correction gather and final out_sum — all in one kernel (no gate, no extra
// launch).
// ---------------------------------------------------------------------------
__global__ __launch_bounds__(256) void k23_kernel(const float* __restrict__ x,
                                                  float* __restrict__ out_a,
                                                  float* __restrict__ out_sum)
{
    const int b    = blockIdx.x;
    const int t    = threadIdx.x;
    const int warp = t >> 5;
    const int lane = t & 31;

    float wreg[32];
#pragma unroll
    for (int j = 0; j < 32; j++) wreg[j] = g_w[b * SS + j * 256 + t];

    __shared__ float sredf[8];
    __shared__ float sZ;
    __shared__ int   stot[32];
    __shared__ float sPsum[DD];
    if (t < 32) stot[t] = 0;

    // Z = sum(w)
    float z = 0.f;
#pragma unroll
    for (int j = 0; j < 32; j++) z += wreg[j];
#pragma unroll
    for (int off = 16; off; off >>= 1) z += __shfl_xor_sync(0xffffffffu, z, off);
    if (lane == 0) sredf[warp] = z;
    __syncthreads();
    if (t == 0) {
        float zz = 0.f;
        for (int i = 0; i < 8; i++) zz += sredf[i];
        sZ = zz;
    }

    // P chunk-reduction (overlaps the barrier shadow)
    {
        float p = 0.f;
#pragma unroll
        for (int c = 0; c < NCHUNK; c++)
            p += g_Ppart[((size_t)c * BB + b) * DD + t];
        sPsum[t] = p;
    }
    __syncthreads();
    const float invZ = 1.f / sZ;

    // exact KSEL-th largest via binary search on float bit patterns
    unsigned lo = 0x3E800000u;  // 0.25f
    unsigned hi = 0x40800000u;  // 4.0f
    int it = 0;
    while (hi - lo > 1u) {
        const unsigned mid = lo + ((hi - lo) >> 1);
        const float fm = __uint_as_float(mid);
        int c = 0;
#pragma unroll
        for (int j = 0; j < 32; j++) c += (wreg[j] >= fm);
        c = __reduce_add_sync(0xffffffffu, c);
        if (lane == 0) atomicAdd(&stot[it], c);
        __syncthreads();
        if (stot[it] >= KSEL) lo = mid; else hi = mid;
        it++;
    }
    const float thr = __uint_as_float(lo);

    // out_a + correction band membership.
    // thr < THI : rows w in [thr, THI)  under-emphasized -> +0.5*w
    // thr > THI : rows w in [THI, thr)  over-emphasized  -> -0.5*w
    const float tlo  = fminf(thr, THI);
    const float thi2 = fmaxf(thr, THI);
    const float sgn  = (thr < THI) ? 0.5f : -0.5f;

    unsigned bandmask = 0u;
    int cnt = 0;
#pragma unroll
    for (int j = 0; j < 32; j++) {
        const float wv = wreg[j];
        out_a[b * SS + j * 256 + t] = wv * invZ * ((wv >= thr) ? 1.5f : 1.0f);
        const bool inband = (wv >= tlo) && (wv < thi2);
        bandmask |= (inband ? 1u : 0u) << j;
        cnt += inband ? 1 : 0;
    }

    // deterministic ordered compaction of correction rows (block-local slice)
    int v2 = cnt;
#pragma unroll
    for (int off = 1; off < 32; off <<= 1) {
        const int n = __shfl_up_sync(0xffffffffu, v2, off);
        if (lane >= off) v2 += n;
    }
    __shared__ int swsum[8];
    __shared__ int swbase[8];
    __shared__ int scnt;
    if (lane == 31) swsum[warp] = v2;
    __syncthreads();
    if (t == 0) {
        int s = 0;
        for (int i = 0; i < 8; i++) { swbase[i] = s; s += swsum[i]; }
        scnt = s;
    }
    __syncthreads();
    {
        int base = swbase[warp] + v2 - cnt;
        int*   dsti = g_idx + b * SS;
        float* dstw = g_wc  + b * SS;
#pragma unroll
        for (int j = 0; j < 32; j++) {
            if ((bandmask >> j) & 1u) {
                dsti[base] = j * 256 + t;
                dstw[base] = sgn * wreg[j];
                base++;
            }
        }
    }
    __syncthreads();   // makes this block's global writes visible block-wide
    const int cntE = scnt;

    // ---- correction gather: warp g takes slots g, g+8, ... ----
    const int*   idx = g_idx + b * SS;
    const float* wc  = g_wc  + b * SS;
    const float4* xb = (const float4*)(x + (size_t)b * SS * DD);

    float acc[8];
#pragma unroll
    for (int j = 0; j < 8; j++) acc[j] = 0.f;

    for (int sbase = warp; sbase < cntE; sbase += 4 * 8) {
        int   rr[4];
        float ww[4];
#pragma unroll
        for (int k = 0; k < 4; k++) {
            const int s = sbase + k * 8;
            const bool vld = (s < cntE);
            rr[k] = vld ? idx[s] : 0;
            ww[k] = vld ? wc[s]  : 0.f;
        }
#pragma unroll
        for (int k = 0; k < 4; k++) {    // branchless: LDGs batch
            const float4* x0 = xb + (size_t)rr[k] * (DD / 4);
            const float4 a0 = x0[lane];
            const float4 a1 = x0[32 + lane];
            const float w0 = ww[k];
            acc[0] += a0.x * w0; acc[1] += a0.y * w0;
            acc[2] += a0.z * w0; acc[3] += a0.w * w0;
            acc[4] += a1.x * w0; acc[5] += a1.y * w0;
            acc[6] += a1.z * w0; acc[7] += a1.w * w0;
        }
    }

    __shared__ float sacc[8][DD];
#pragma unroll
    for (int j = 0; j < 4; j++) {
        sacc[warp][lane * 4 + j]       = acc[j];
        sacc[warp][128 + lane * 4 + j] = acc[4 + j];
    }
    __syncthreads();
    {
        float csum = 0.f;
#pragma unroll
        for (int wp = 0; wp < 8; wp++) csum += sacc[wp][t];
        out_sum[b * DD + t] = invZ * (sPsum[t] + csum);
    }
}

// ---------------------------------------------------------------------------
extern "C" void kernel_launch(void* const* d_in, const int* in_sizes, int n_in,
                              void* d_out, int out_size)
{
    const float* x    = (const float*)d_in[0];
    const float* W    = (const float*)d_in[1];
    const float* bias = (const float*)d_in[2];

    float* out      = (float*)d_out;
    float* out_sum  = out;              // [BB, DD]
    float* out_a    = out + BB * DD;    // [BB, SS]

    k1_kernel<<<BB * NCHUNK, 256>>>(x, W, bias);
    k23_kernel<<<BB, 256>>>(x, out_a, out_sum);
}